// round 2
// baseline (speedup 1.0000x reference)
#include <cuda_runtime.h>
#include <math.h>

#define Bsz  2
#define Nseq 2048
#define Emb  1024
#define Hh   16
#define Dh   64

// Scratch (allocation-free: __device__ globals)
__device__ float g_q [Bsz * Hh * Nseq * Dh];   // [B,H,N,D]
__device__ float g_k [Bsz * Hh * Nseq * Dh];
__device__ float g_v [Bsz * Hh * Nseq * Dh];
__device__ float g_ao[Bsz * Nseq * Hh * Dh];   // [B,N,H*D]

// ---------------------------------------------------------------------------
// GEMM: C[r][c] = sum_k A[r][k] * W[c][k] + bias[c]
// A: [4096, 1024] row-major, W: [Ncols, 1024] row-major.
// MODE 0: epilogue scatters into g_q/g_k/g_v per (h,d,s) interleave.
// MODE 1: A is g_ao, epilogue writes plain to `out`.
// Tiling: 128x128x8, 256 threads, 8x8 per thread.
// ---------------------------------------------------------------------------
template <int MODE>
__global__ void __launch_bounds__(256) gemm_kernel(const float* __restrict__ A,
                                                   const float* __restrict__ W,
                                                   const float* __restrict__ bias,
                                                   float* __restrict__ out)
{
    __shared__ float As[8][128];
    __shared__ float Ws[8][128];

    const float* Asrc = (MODE == 0) ? A : g_ao;

    const int tid = threadIdx.x;
    const int bm = blockIdx.y * 128;
    const int bn = blockIdx.x * 128;

    const int lrow = tid >> 1;          // 0..127
    const int lc4  = (tid & 1) * 4;     // 0 or 4
    const int ty   = tid >> 4;          // 0..15
    const int tx   = tid & 15;          // 0..15

    const float* Ap = Asrc + (size_t)(bm + lrow) * Emb + lc4;
    const float* Wp = W    + (size_t)(bn + lrow) * Emb + lc4;

    float acc[8][8];
#pragma unroll
    for (int i = 0; i < 8; i++)
#pragma unroll
        for (int j = 0; j < 8; j++) acc[i][j] = 0.f;

    for (int k0 = 0; k0 < Emb; k0 += 8) {
        float4 av = *(const float4*)(Ap + k0);
        float4 wv = *(const float4*)(Wp + k0);
        As[lc4 + 0][lrow] = av.x; As[lc4 + 1][lrow] = av.y;
        As[lc4 + 2][lrow] = av.z; As[lc4 + 3][lrow] = av.w;
        Ws[lc4 + 0][lrow] = wv.x; Ws[lc4 + 1][lrow] = wv.y;
        Ws[lc4 + 2][lrow] = wv.z; Ws[lc4 + 3][lrow] = wv.w;
        __syncthreads();

#pragma unroll
        for (int kk = 0; kk < 8; kk++) {
            float a[8], b[8];
            *(float4*)&a[0] = *(const float4*)&As[kk][ty * 8];
            *(float4*)&a[4] = *(const float4*)&As[kk][ty * 8 + 4];
            *(float4*)&b[0] = *(const float4*)&Ws[kk][tx * 8];
            *(float4*)&b[4] = *(const float4*)&Ws[kk][tx * 8 + 4];
#pragma unroll
            for (int i = 0; i < 8; i++)
#pragma unroll
                for (int j = 0; j < 8; j++)
                    acc[i][j] = fmaf(a[i], b[j], acc[i][j]);
        }
        __syncthreads();
    }

    if (MODE == 0) {
        // scatter into q/k/v: col c -> h = c/192, d = (c%192)/3, s = c%3
#pragma unroll
        for (int i = 0; i < 8; i++) {
            const int row = bm + ty * 8 + i;
            const int b   = row >> 11;
            const int n   = row & 2047;
#pragma unroll
            for (int j = 0; j < 8; j++) {
                const int c = bn + tx * 8 + j;
                const int s = c % 3;
                const int h = c / 192;
                const int d = (c % 192) / 3;
                const float val = acc[i][j] + bias[c];
                float* dst = (s == 0) ? g_q : (s == 1) ? g_k : g_v;
                dst[(((size_t)(b * Hh + h)) * Nseq + n) * Dh + d] = val;
            }
        }
    } else {
#pragma unroll
        for (int i = 0; i < 8; i++) {
            const int row = bm + ty * 8 + i;
            float* dst = out + (size_t)row * Emb + bn + tx * 8;
#pragma unroll
            for (int j = 0; j < 8; j++)
                dst[j] = acc[i][j] + bias[bn + tx * 8 + j];
        }
    }
}

// ---------------------------------------------------------------------------
// Flash attention, fp32, causal. grid = (N/64, B*H), 256 threads.
// BR=64 query rows, BC=32 key cols per inner tile, D=64.
// ---------------------------------------------------------------------------
__global__ void __launch_bounds__(256) flash_kernel()
{
    __shared__ float Qs[64][68];
    __shared__ float Ks[32][68];
    __shared__ float Vs[32][68];
    __shared__ float Ss[64][36];
    __shared__ float rescale_s[64];
    __shared__ float l_s[64];

    const int tid = threadIdx.x;
    const int qb  = blockIdx.x;           // query block (64 rows)
    const int bh  = blockIdx.y;           // b*16 + h

    const float* Qg = g_q + ((size_t)bh * Nseq + qb * 64) * Dh;
    const float* Kg = g_k + (size_t)bh * Nseq * Dh;
    const float* Vg = g_v + (size_t)bh * Nseq * Dh;

    const float scale = 0.125f;           // D^-0.5

    // Load & pre-scale Q tile (64x64)
    for (int i = tid; i < 64 * 16; i += 256) {
        const int r = i >> 4, c4 = (i & 15) * 4;
        float4 q = *(const float4*)(Qg + r * Dh + c4);
        Qs[r][c4 + 0] = q.x * scale; Qs[r][c4 + 1] = q.y * scale;
        Qs[r][c4 + 2] = q.z * scale; Qs[r][c4 + 3] = q.w * scale;
    }

    float m_r = -INFINITY, l_r = 0.f;     // valid for tid < 64 (row owners)

    float o[4][4];
#pragma unroll
    for (int i = 0; i < 4; i++)
#pragma unroll
        for (int j = 0; j < 4; j++) o[i][j] = 0.f;

    const int tr = tid >> 3;              // 0..31 -> rows tr*2, tr*2+1
    const int tc = tid & 7;               // cols tc*4 .. +3
    const int r0 = (tid >> 4) * 4;        // O rows
    const int c0 = (tid & 15) * 4;        // O cols (head dim)

    const int ntiles = 2 * qb + 2;
    for (int j = 0; j < ntiles; j++) {
        const float* Kt = Kg + (size_t)j * 32 * Dh;
        const float* Vt = Vg + (size_t)j * 32 * Dh;
        for (int i = tid; i < 32 * 16; i += 256) {
            const int r = i >> 4, c4 = (i & 15) * 4;
            *(float4*)&Ks[r][c4] = *(const float4*)(Kt + r * Dh + c4);
            *(float4*)&Vs[r][c4] = *(const float4*)(Vt + r * Dh + c4);
        }
        __syncthreads();

        // S = Qs * Ks^T  (this thread: 2 rows x 4 cols)
        float s0[4] = {0.f, 0.f, 0.f, 0.f};
        float s1[4] = {0.f, 0.f, 0.f, 0.f};
#pragma unroll
        for (int k = 0; k < 64; k += 4) {
            const float4 qv0 = *(const float4*)&Qs[tr * 2][k];
            const float4 qv1 = *(const float4*)&Qs[tr * 2 + 1][k];
#pragma unroll
            for (int jj = 0; jj < 4; jj++) {
                const float4 kv = *(const float4*)&Ks[tc * 4 + jj][k];
                s0[jj] = fmaf(qv0.x, kv.x, fmaf(qv0.y, kv.y, fmaf(qv0.z, kv.z, fmaf(qv0.w, kv.w, s0[jj]))));
                s1[jj] = fmaf(qv1.x, kv.x, fmaf(qv1.y, kv.y, fmaf(qv1.z, kv.z, fmaf(qv1.w, kv.w, s1[jj]))));
            }
        }
        const bool domask = (j >= 2 * qb);
        const int rowg = qb * 64 + tr * 2;
#pragma unroll
        for (int jj = 0; jj < 4; jj++) {
            const int colg = j * 32 + tc * 4 + jj;
            float v0 = s0[jj], v1 = s1[jj];
            if (domask) {
                if (colg > rowg)     v0 = -INFINITY;
                if (colg > rowg + 1) v1 = -INFINITY;
            }
            Ss[tr * 2][tc * 4 + jj]     = v0;
            Ss[tr * 2 + 1][tc * 4 + jj] = v1;
        }
        __syncthreads();

        // Online softmax: one row per thread (tid < 64)
        if (tid < 64) {
            float mt = m_r;
#pragma unroll
            for (int c = 0; c < 32; c++) mt = fmaxf(mt, Ss[tid][c]);
            const float sc = __expf(m_r - mt);   // first iter: exp(-inf)=0
            float ps = 0.f;
#pragma unroll
            for (int c = 0; c < 32; c++) {
                const float p = __expf(Ss[tid][c] - mt);
                Ss[tid][c] = p;
                ps += p;
            }
            l_r = l_r * sc + ps;
            m_r = mt;
            rescale_s[tid] = sc;
        }
        __syncthreads();

        // O = O*rescale + P*V   (this thread: rows r0..r0+3, cols c0..c0+3)
        const float rs0 = rescale_s[r0], rs1 = rescale_s[r0 + 1];
        const float rs2 = rescale_s[r0 + 2], rs3 = rescale_s[r0 + 3];
#pragma unroll
        for (int jj = 0; jj < 4; jj++) {
            o[0][jj] *= rs0; o[1][jj] *= rs1; o[2][jj] *= rs2; o[3][jj] *= rs3;
        }
#pragma unroll
        for (int c = 0; c < 32; c++) {
            const float4 vv = *(const float4*)&Vs[c][c0];
            const float p0 = Ss[r0][c], p1 = Ss[r0 + 1][c];
            const float p2 = Ss[r0 + 2][c], p3 = Ss[r0 + 3][c];
            o[0][0] = fmaf(p0, vv.x, o[0][0]); o[0][1] = fmaf(p0, vv.y, o[0][1]);
            o[0][2] = fmaf(p0, vv.z, o[0][2]); o[0][3] = fmaf(p0, vv.w, o[0][3]);
            o[1][0] = fmaf(p1, vv.x, o[1][0]); o[1][1] = fmaf(p1, vv.y, o[1][1]);
            o[1][2] = fmaf(p1, vv.z, o[1][2]); o[1][3] = fmaf(p1, vv.w, o[1][3]);
            o[2][0] = fmaf(p2, vv.x, o[2][0]); o[2][1] = fmaf(p2, vv.y, o[2][1]);
            o[2][2] = fmaf(p2, vv.z, o[2][2]); o[2][3] = fmaf(p2, vv.w, o[2][3]);
            o[3][0] = fmaf(p3, vv.x, o[3][0]); o[3][1] = fmaf(p3, vv.y, o[3][1]);
            o[3][2] = fmaf(p3, vv.z, o[3][2]); o[3][3] = fmaf(p3, vv.w, o[3][3]);
        }
        __syncthreads();
    }

    if (tid < 64) l_s[tid] = l_r;
    __syncthreads();

    const int b = bh >> 4, h = bh & 15;
#pragma unroll
    for (int i = 0; i < 4; i++) {
        const float inv = 1.f / l_s[r0 + i];
        const int n = qb * 64 + r0 + i;
        float4 ov;
        ov.x = o[i][0] * inv; ov.y = o[i][1] * inv;
        ov.z = o[i][2] * inv; ov.w = o[i][3] * inv;
        *(float4*)(g_ao + ((size_t)(b * Nseq + n)) * (Hh * Dh) + h * Dh + c0) = ov;
    }
}

// ---------------------------------------------------------------------------
extern "C" void kernel_launch(void* const* d_in, const int* in_sizes, int n_in,
                              void* d_out, int out_size)
{
    const float* x    = (const float*)d_in[0];
    const float* Wqkv = (const float*)d_in[1];
    const float* bqkv = (const float*)d_in[2];
    const float* Wout = (const float*)d_in[3];
    const float* bout = (const float*)d_in[4];
    float* out = (float*)d_out;

    // K1: QKV projection + de-interleave scatter. C is [4096, 3072].
    gemm_kernel<0><<<dim3(3072 / 128, 4096 / 128), 256>>>(x, Wqkv, bqkv, nullptr);

    // K2: causal flash attention. grid (N/64, B*H).
    flash_kernel<<<dim3(Nseq / 64, Bsz * Hh), 256>>>();

    // K3: output projection. C is [4096, 1024].
    gemm_kernel<1><<<dim3(1024 / 128, 4096 / 128), 256>>>(nullptr, Wout, bout, out);
}

// round 3
// speedup vs baseline: 3.9916x; 3.9916x over previous
#include <cuda_runtime.h>
#include <math.h>

#define Bsz  2
#define Nseq 2048
#define Emb  1024
#define Hh   16
#define Dh   64

// Scratch (allocation-free: __device__ globals)
__device__ float g_q [Bsz * Hh * Nseq * Dh];   // [B,H,N,D]
__device__ float g_k [Bsz * Hh * Nseq * Dh];
__device__ float g_v [Bsz * Hh * Nseq * Dh];
__device__ float g_ao[Bsz * Nseq * Hh * Dh];   // [B,N,H*D]

// ---------------------------------------------------------------------------
// helpers
// ---------------------------------------------------------------------------
__device__ __forceinline__ float f2tf32(float f) {
    unsigned r;
    asm("cvt.rna.tf32.f32 %0, %1;" : "=r"(r) : "f"(f));
    return __uint_as_float(r);
}

__device__ __forceinline__ void mma_tf32(float* c, const unsigned* a, const unsigned* b) {
    asm volatile(
        "mma.sync.aligned.m16n8k8.row.col.f32.tf32.tf32.f32 "
        "{%0,%1,%2,%3},{%4,%5,%6,%7},{%8,%9},{%0,%1,%2,%3};"
        : "+f"(c[0]), "+f"(c[1]), "+f"(c[2]), "+f"(c[3])
        : "r"(a[0]), "r"(a[1]), "r"(a[2]), "r"(a[3]), "r"(b[0]), "r"(b[1]));
}

// ---------------------------------------------------------------------------
// TF32 GEMM: C[r][c] = sum_k A[r][k] * W[c][k] + bias[c]
// 128x128 block tile, BK=32, 256 threads = 8 warps (4 x 2), warp tile 32x64.
// MODE 0: epilogue scatters into g_q/g_k/g_v; MODE 1: plain write to out.
// ---------------------------------------------------------------------------
template <int MODE>
__global__ void __launch_bounds__(256) gemm_tf32_kernel(const float* __restrict__ A,
                                                        const float* __restrict__ W,
                                                        const float* __restrict__ bias,
                                                        float* __restrict__ out)
{
    __shared__ float As[128][36];
    __shared__ float Ws[128][36];

    const float* Asrc = (MODE == 0) ? A : g_ao;

    const int tid  = threadIdx.x;
    const int lane = tid & 31;
    const int warp = tid >> 5;
    const int wm   = warp & 3;         // 0..3 : 32-row group
    const int wn   = warp >> 2;        // 0..1 : 64-col group
    const int bm = blockIdx.y * 128;
    const int bn = blockIdx.x * 128;

    const int gid = lane >> 2;         // 0..7
    const int tig = lane & 3;          // 0..3

    float acc[2][8][4];
#pragma unroll
    for (int mi = 0; mi < 2; mi++)
#pragma unroll
        for (int nj = 0; nj < 8; nj++)
#pragma unroll
            for (int q = 0; q < 4; q++) acc[mi][nj][q] = 0.f;

    for (int k0 = 0; k0 < Emb; k0 += 32) {
        // load 128x32 tiles of A and W, convert to tf32
#pragma unroll
        for (int i = 0; i < 4; i++) {
            const int idx = tid + i * 256;          // float4 index, 1024 total
            const int row = idx >> 3;
            const int c4  = (idx & 7) * 4;
            float4 av = *(const float4*)(Asrc + (size_t)(bm + row) * Emb + k0 + c4);
            float4 wv = *(const float4*)(W    + (size_t)(bn + row) * Emb + k0 + c4);
            As[row][c4 + 0] = f2tf32(av.x); As[row][c4 + 1] = f2tf32(av.y);
            As[row][c4 + 2] = f2tf32(av.z); As[row][c4 + 3] = f2tf32(av.w);
            Ws[row][c4 + 0] = f2tf32(wv.x); Ws[row][c4 + 1] = f2tf32(wv.y);
            Ws[row][c4 + 2] = f2tf32(wv.z); Ws[row][c4 + 3] = f2tf32(wv.w);
        }
        __syncthreads();

#pragma unroll
        for (int kk = 0; kk < 32; kk += 8) {
            unsigned afrag[2][4];
#pragma unroll
            for (int mi = 0; mi < 2; mi++) {
                const int rb = wm * 32 + mi * 16;
                afrag[mi][0] = __float_as_uint(As[rb + gid    ][kk + tig    ]);
                afrag[mi][1] = __float_as_uint(As[rb + 8 + gid][kk + tig    ]);
                afrag[mi][2] = __float_as_uint(As[rb + gid    ][kk + tig + 4]);
                afrag[mi][3] = __float_as_uint(As[rb + 8 + gid][kk + tig + 4]);
            }
            unsigned bfrag[8][2];
#pragma unroll
            for (int nj = 0; nj < 8; nj++) {
                const int cb = wn * 64 + nj * 8;
                bfrag[nj][0] = __float_as_uint(Ws[cb + gid][kk + tig    ]);
                bfrag[nj][1] = __float_as_uint(Ws[cb + gid][kk + tig + 4]);
            }
#pragma unroll
            for (int mi = 0; mi < 2; mi++)
#pragma unroll
                for (int nj = 0; nj < 8; nj++)
                    mma_tf32(acc[mi][nj], afrag[mi], bfrag[nj]);
        }
        __syncthreads();
    }

    // epilogue
#pragma unroll
    for (int mi = 0; mi < 2; mi++) {
        const int r_top = bm + wm * 32 + mi * 16 + gid;
        const int r_bot = r_top + 8;
#pragma unroll
        for (int nj = 0; nj < 8; nj++) {
            const int c = bn + wn * 64 + nj * 8 + 2 * tig;
            if (MODE == 0) {
#pragma unroll
                for (int q = 0; q < 4; q++) {
                    const int row = (q < 2) ? r_top : r_bot;
                    const int col = c + (q & 1);
                    const int b = row >> 11;
                    const int n = row & 2047;
                    const int s = col % 3;
                    const int h = col / 192;
                    const int d = (col % 192) / 3;
                    const float val = acc[mi][nj][q] + bias[col];
                    float* dst = (s == 0) ? g_q : (s == 1) ? g_k : g_v;
                    dst[(((size_t)(b * Hh + h)) * Nseq + n) * Dh + d] = val;
                }
            } else {
                const float2 bv = *(const float2*)(bias + c);
                float2 v0, v1;
                v0.x = acc[mi][nj][0] + bv.x; v0.y = acc[mi][nj][1] + bv.y;
                v1.x = acc[mi][nj][2] + bv.x; v1.y = acc[mi][nj][3] + bv.y;
                *(float2*)(out + (size_t)r_top * Emb + c) = v0;
                *(float2*)(out + (size_t)r_bot * Emb + c) = v1;
            }
        }
    }
}

// ---------------------------------------------------------------------------
// Flash attention, TF32 mma for S=QK^T and P*V, SIMT online softmax.
// grid = (N/64, B*H), 128 threads = 4 warps. BR=64, BC=32, D=64.
// Warp w owns S/O rows w*16 .. w*16+15.
// ---------------------------------------------------------------------------
__global__ void __launch_bounds__(128) flash_kernel()
{
    __shared__ float Qs[64][68];
    __shared__ float Ks[32][68];
    __shared__ float Vs[32][68];
    __shared__ float Ss[64][36];
    __shared__ float rescale_s[64];
    __shared__ float l_s[64];

    const int tid  = threadIdx.x;
    const int lane = tid & 31;
    const int w    = tid >> 5;
    const int gid  = lane >> 2;
    const int tig  = lane & 3;

    const int qb = (gridDim.x - 1) - blockIdx.x;   // heaviest blocks first
    const int bh = blockIdx.y;

    const float* Qg = g_q + ((size_t)bh * Nseq + qb * 64) * Dh;
    const float* Kg = g_k + (size_t)bh * Nseq * Dh;
    const float* Vg = g_v + (size_t)bh * Nseq * Dh;

    const float scale = 0.125f;

    // Load & pre-scale Q tile (64x64), tf32-rounded
#pragma unroll
    for (int i = 0; i < 8; i++) {
        const int idx = tid + i * 128;   // float4 idx, 1024 total
        const int r = idx >> 4, c4 = (idx & 15) * 4;
        float4 q = *(const float4*)(Qg + r * Dh + c4);
        Qs[r][c4 + 0] = f2tf32(q.x * scale); Qs[r][c4 + 1] = f2tf32(q.y * scale);
        Qs[r][c4 + 2] = f2tf32(q.z * scale); Qs[r][c4 + 3] = f2tf32(q.w * scale);
    }

    float m_r = -INFINITY, l_r = 0.f;   // for tid < 64 (row owners)

    float oacc[8][4];
#pragma unroll
    for (int nj = 0; nj < 8; nj++)
#pragma unroll
        for (int q = 0; q < 4; q++) oacc[nj][q] = 0.f;

    const int ntiles = 2 * qb + 2;
    for (int j = 0; j < ntiles; j++) {
        const float* Kt = Kg + (size_t)j * 32 * Dh;
        const float* Vt = Vg + (size_t)j * 32 * Dh;
#pragma unroll
        for (int i = 0; i < 4; i++) {
            const int idx = tid + i * 128;   // float4 idx, 512 per tensor
            const int r = idx >> 4, c4 = (idx & 15) * 4;
            float4 kv = *(const float4*)(Kt + r * Dh + c4);
            float4 vv = *(const float4*)(Vt + r * Dh + c4);
            Ks[r][c4 + 0] = f2tf32(kv.x); Ks[r][c4 + 1] = f2tf32(kv.y);
            Ks[r][c4 + 2] = f2tf32(kv.z); Ks[r][c4 + 3] = f2tf32(kv.w);
            Vs[r][c4 + 0] = f2tf32(vv.x); Vs[r][c4 + 1] = f2tf32(vv.y);
            Vs[r][c4 + 2] = f2tf32(vv.z); Vs[r][c4 + 3] = f2tf32(vv.w);
        }
        __syncthreads();

        // ---- S = Qs * Ks^T : warp rows w*16..+15, cols 0..31 ----
        float sacc[4][4];
#pragma unroll
        for (int nj = 0; nj < 4; nj++)
#pragma unroll
            for (int q = 0; q < 4; q++) sacc[nj][q] = 0.f;

#pragma unroll
        for (int kk = 0; kk < 64; kk += 8) {
            unsigned af[4];
            const int rb = w * 16;
            af[0] = __float_as_uint(Qs[rb + gid    ][kk + tig    ]);
            af[1] = __float_as_uint(Qs[rb + 8 + gid][kk + tig    ]);
            af[2] = __float_as_uint(Qs[rb + gid    ][kk + tig + 4]);
            af[3] = __float_as_uint(Qs[rb + 8 + gid][kk + tig + 4]);
#pragma unroll
            for (int nj = 0; nj < 4; nj++) {
                unsigned bf[2];
                bf[0] = __float_as_uint(Ks[nj * 8 + gid][kk + tig    ]);
                bf[1] = __float_as_uint(Ks[nj * 8 + gid][kk + tig + 4]);
                mma_tf32(sacc[nj], af, bf);
            }
        }

        // mask + store fragments to Ss
        const bool domask = (j >= 2 * qb);
        const int r0g = qb * 64 + w * 16 + gid;
        const int r1g = r0g + 8;
#pragma unroll
        for (int nj = 0; nj < 4; nj++) {
            const int cg = j * 32 + nj * 8 + 2 * tig;
            float v0 = sacc[nj][0], v1 = sacc[nj][1];
            float v2 = sacc[nj][2], v3 = sacc[nj][3];
            if (domask) {
                if (cg     > r0g) v0 = -INFINITY;
                if (cg + 1 > r0g) v1 = -INFINITY;
                if (cg     > r1g) v2 = -INFINITY;
                if (cg + 1 > r1g) v3 = -INFINITY;
            }
            float2 t0; t0.x = v0; t0.y = v1;
            float2 t1; t1.x = v2; t1.y = v3;
            *(float2*)&Ss[w * 16 + gid    ][nj * 8 + 2 * tig] = t0;
            *(float2*)&Ss[w * 16 + 8 + gid][nj * 8 + 2 * tig] = t1;
        }
        __syncthreads();

        // ---- online softmax, one row per thread (tid < 64) ----
        if (tid < 64) {
            float mt = m_r;
#pragma unroll
            for (int c = 0; c < 32; c++) mt = fmaxf(mt, Ss[tid][c]);
            const float sc = __expf(m_r - mt);
            float ps = 0.f;
#pragma unroll
            for (int c = 0; c < 32; c++) {
                const float p = __expf(Ss[tid][c] - mt);
                Ss[tid][c] = f2tf32(p);        // pre-round for the PV mma
                ps += p;
            }
            l_r = l_r * sc + ps;
            m_r = mt;
            rescale_s[tid] = sc;
        }
        __syncthreads();

        // ---- O = O*rescale + P*V ----
        const float rs_top = rescale_s[w * 16 + gid];
        const float rs_bot = rescale_s[w * 16 + 8 + gid];
#pragma unroll
        for (int nj = 0; nj < 8; nj++) {
            oacc[nj][0] *= rs_top; oacc[nj][1] *= rs_top;
            oacc[nj][2] *= rs_bot; oacc[nj][3] *= rs_bot;
        }
#pragma unroll
        for (int kk = 0; kk < 32; kk += 8) {
            unsigned af[4];
            const int rb = w * 16;
            af[0] = __float_as_uint(Ss[rb + gid    ][kk + tig    ]);
            af[1] = __float_as_uint(Ss[rb + 8 + gid][kk + tig    ]);
            af[2] = __float_as_uint(Ss[rb + gid    ][kk + tig + 4]);
            af[3] = __float_as_uint(Ss[rb + 8 + gid][kk + tig + 4]);
#pragma unroll
            for (int nj = 0; nj < 8; nj++) {
                unsigned bf[2];
                bf[0] = __float_as_uint(Vs[kk + tig    ][nj * 8 + gid]);
                bf[1] = __float_as_uint(Vs[kk + 4 + tig][nj * 8 + gid]);
                mma_tf32(oacc[nj], af, bf);
            }
        }
        __syncthreads();
    }

    if (tid < 64) l_s[tid] = l_r;
    __syncthreads();

    const int b = bh >> 4, h = bh & 15;
    const float inv_top = 1.f / l_s[w * 16 + gid];
    const float inv_bot = 1.f / l_s[w * 16 + 8 + gid];
    const int n_top = qb * 64 + w * 16 + gid;
    const int n_bot = n_top + 8;
#pragma unroll
    for (int nj = 0; nj < 8; nj++) {
        const int c = nj * 8 + 2 * tig;
        float2 v0, v1;
        v0.x = oacc[nj][0] * inv_top; v0.y = oacc[nj][1] * inv_top;
        v1.x = oacc[nj][2] * inv_bot; v1.y = oacc[nj][3] * inv_bot;
        *(float2*)(g_ao + ((size_t)(b * Nseq + n_top)) * (Hh * Dh) + h * Dh + c) = v0;
        *(float2*)(g_ao + ((size_t)(b * Nseq + n_bot)) * (Hh * Dh) + h * Dh + c) = v1;
    }
}

// ---------------------------------------------------------------------------
extern "C" void kernel_launch(void* const* d_in, const int* in_sizes, int n_in,
                              void* d_out, int out_size)
{
    const float* x    = (const float*)d_in[0];
    const float* Wqkv = (const float*)d_in[1];
    const float* bqkv = (const float*)d_in[2];
    const float* Wout = (const float*)d_in[3];
    const float* bout = (const float*)d_in[4];
    float* out = (float*)d_out;

    // K1: QKV projection + de-interleave scatter. C is [4096, 3072].
    gemm_tf32_kernel<0><<<dim3(3072 / 128, 4096 / 128), 256>>>(x, Wqkv, bqkv, nullptr);

    // K2: causal flash attention. grid (N/64, B*H).
    flash_kernel<<<dim3(Nseq / 64, Bsz * Hh), 128>>>();

    // K3: output projection. C is [4096, 1024].
    gemm_tf32_kernel<1><<<dim3(1024 / 128, 4096 / 128), 256>>>(nullptr, Wout, bout, out);
}

// round 4
// speedup vs baseline: 4.6237x; 1.1584x over previous
#include <cuda_runtime.h>
#include <math.h>

#define Bsz  2
#define Nseq 2048
#define Emb  1024
#define Hh   16
#define Dh   64

// Scratch (allocation-free: __device__ globals)
__device__ float g_q [Bsz * Hh * Nseq * Dh];   // [B,H,N,D]
__device__ float g_k [Bsz * Hh * Nseq * Dh];
__device__ float g_v [Bsz * Hh * Nseq * Dh];
__device__ float g_ao[Bsz * Nseq * Hh * Dh];   // [B,N,H*D]

// ---------------------------------------------------------------------------
// helpers
// ---------------------------------------------------------------------------
__device__ __forceinline__ float f2tf32(float f) {
    unsigned r;
    asm("cvt.rna.tf32.f32 %0, %1;" : "=r"(r) : "f"(f));
    return __uint_as_float(r);
}

__device__ __forceinline__ void mma_tf32(float* c, const unsigned* a, const unsigned* b) {
    asm volatile(
        "mma.sync.aligned.m16n8k8.row.col.f32.tf32.tf32.f32 "
        "{%0,%1,%2,%3},{%4,%5,%6,%7},{%8,%9},{%0,%1,%2,%3};"
        : "+f"(c[0]), "+f"(c[1]), "+f"(c[2]), "+f"(c[3])
        : "r"(a[0]), "r"(a[1]), "r"(a[2]), "r"(a[3]), "r"(b[0]), "r"(b[1]));
}

// Fragment-ordered smem layouts
// A-chunk (16 rows x 8 k): 132 floats. element addr = chunk*132 + (gid*4+tig)*4 + slot,
//   slot = half + 2*khalf  (half = rowin/8, khalf = (kin%8)/4, tig = kin%4, gid = rowin%8)
// B-chunk (8 cols x 8 k): 66 floats. element addr = chunk*66 + (gidb*4+tig)*2 + khalf

// ---------------------------------------------------------------------------
// TF32 GEMM: C[r][c] = sum_k A[r][k] * W[c][k] + bias[c]
// 128x128 block tile, BK=32, 256 threads = 8 warps (4 x 2), warp tile 32x64.
// Fragment-ordered smem + register double buffering of global loads.
// ---------------------------------------------------------------------------
template <int MODE>
__global__ void __launch_bounds__(256) gemm_tf32_kernel(const float* __restrict__ A,
                                                        const float* __restrict__ W,
                                                        const float* __restrict__ bias,
                                                        float* __restrict__ out)
{
    __shared__ __align__(16) float As[32 * 132];  // chunks (m 0..7, kg 0..3)
    __shared__ __align__(16) float Ws[64 * 66];   // chunks (nb 0..15, kg 0..3)

    const float* Asrc = (MODE == 0) ? A : g_ao;

    const int tid  = threadIdx.x;
    const int lane = tid & 31;
    const int warp = tid >> 5;
    const int wm   = warp & 3;         // 0..3 : 32-row group
    const int wn   = warp >> 2;        // 0..1 : 64-col group
    const int bm = blockIdx.y * 128;
    const int bn = blockIdx.x * 128;

    const int gid = lane >> 2;         // 0..7
    const int tig = lane & 3;          // 0..3

    float acc[2][8][4];
#pragma unroll
    for (int mi = 0; mi < 2; mi++)
#pragma unroll
        for (int nj = 0; nj < 8; nj++)
#pragma unroll
            for (int q = 0; q < 4; q++) acc[mi][nj][q] = 0.f;

    float4 aS[4], wS[4];               // staging regs

    auto ldg_tile = [&](int k0) {
#pragma unroll
        for (int i = 0; i < 4; i++) {
            const int idx = tid + i * 256;
            const int row = idx >> 3;
            const int c4  = (idx & 7) * 4;
            aS[i] = *(const float4*)(Asrc + (size_t)(bm + row) * Emb + k0 + c4);
            wS[i] = *(const float4*)(W    + (size_t)(bn + row) * Emb + k0 + c4);
        }
    };
    auto sts_tile = [&]() {
#pragma unroll
        for (int i = 0; i < 4; i++) {
            const int idx = tid + i * 256;
            const int row = idx >> 3;
            const int c4  = (idx & 7) * 4;
            const int kg  = c4 >> 3;
            const int kh  = (c4 >> 2) & 1;
            // A store
            {
                const int m    = row >> 4;
                const int gidl = row & 7;
                const int half = (row >> 3) & 1;
                float* ap = As + (m * 4 + kg) * 132 + half + 2 * kh;
                const float v[4] = {aS[i].x, aS[i].y, aS[i].z, aS[i].w};
#pragma unroll
                for (int u = 0; u < 4; u++)
                    ap[(gidl * 4 + u) * 4] = f2tf32(v[u]);
            }
            // W store
            {
                const int nb   = row >> 3;
                const int gidb = row & 7;
                float* wp = Ws + (nb * 4 + kg) * 66 + kh;
                const float v[4] = {wS[i].x, wS[i].y, wS[i].z, wS[i].w};
#pragma unroll
                for (int u = 0; u < 4; u++)
                    wp[(gidb * 4 + u) * 2] = f2tf32(v[u]);
            }
        }
    };

    ldg_tile(0);
    for (int kt = 0; kt < Emb / 32; kt++) {
        sts_tile();
        __syncthreads();
        if (kt + 1 < Emb / 32) ldg_tile((kt + 1) * 32);

#pragma unroll
        for (int kk8 = 0; kk8 < 4; kk8++) {
            unsigned afrag[2][4];
#pragma unroll
            for (int mi = 0; mi < 2; mi++) {
                const float4 av = *(const float4*)(As + ((wm * 2 + mi) * 4 + kk8) * 132 + lane * 4);
                afrag[mi][0] = __float_as_uint(av.x); afrag[mi][1] = __float_as_uint(av.y);
                afrag[mi][2] = __float_as_uint(av.z); afrag[mi][3] = __float_as_uint(av.w);
            }
            unsigned bfrag[8][2];
#pragma unroll
            for (int nj = 0; nj < 8; nj++) {
                const float2 bv = *(const float2*)(Ws + ((wn * 8 + nj) * 4 + kk8) * 66 + lane * 2);
                bfrag[nj][0] = __float_as_uint(bv.x); bfrag[nj][1] = __float_as_uint(bv.y);
            }
#pragma unroll
            for (int mi = 0; mi < 2; mi++)
#pragma unroll
                for (int nj = 0; nj < 8; nj++)
                    mma_tf32(acc[mi][nj], afrag[mi], bfrag[nj]);
        }
        __syncthreads();
    }

    // epilogue (same acc mapping as before)
#pragma unroll
    for (int mi = 0; mi < 2; mi++) {
        const int r_top = bm + wm * 32 + mi * 16 + gid;
        const int r_bot = r_top + 8;
#pragma unroll
        for (int nj = 0; nj < 8; nj++) {
            const int c = bn + wn * 64 + nj * 8 + 2 * tig;
            if (MODE == 0) {
#pragma unroll
                for (int q = 0; q < 4; q++) {
                    const int row = (q < 2) ? r_top : r_bot;
                    const int col = c + (q & 1);
                    const int b = row >> 11;
                    const int n = row & 2047;
                    const int s = col % 3;
                    const int h = col / 192;
                    const int d = (col % 192) / 3;
                    const float val = acc[mi][nj][q] + bias[col];
                    float* dst = (s == 0) ? g_q : (s == 1) ? g_k : g_v;
                    dst[(((size_t)(b * Hh + h)) * Nseq + n) * Dh + d] = val;
                }
            } else {
                const float2 bv = *(const float2*)(bias + c);
                float2 v0, v1;
                v0.x = acc[mi][nj][0] + bv.x; v0.y = acc[mi][nj][1] + bv.y;
                v1.x = acc[mi][nj][2] + bv.x; v1.y = acc[mi][nj][3] + bv.y;
                *(float2*)(out + (size_t)r_top * Emb + c) = v0;
                *(float2*)(out + (size_t)r_bot * Emb + c) = v1;
            }
        }
    }
}

// ---------------------------------------------------------------------------
// Flash attention, TF32 mma, register-resident online softmax.
// grid = (N/64, B*H), 128 threads = 4 warps. BR=64, BC=32, D=64.
// Warp w owns S/O rows w*16 .. w*16+15. Row state lives in the 4-lane quad.
// ---------------------------------------------------------------------------
__global__ void __launch_bounds__(128) flash_kernel()
{
    // Fragment-ordered smem
    __shared__ __align__(16) float Qs[32 * 132];  // A-chunks (m 0..3, kg 0..7)
    __shared__ __align__(16) float Ks[32 * 66];   // B-chunks (nb 0..3, kg 0..7)
    __shared__ __align__(16) float Vs[32 * 66];   // B-chunks (nb 0..7 [d], kg 0..3 [c])
    __shared__ __align__(16) float Ss[16 * 132];  // A-chunks per warp (w, kg 0..3)

    const int tid  = threadIdx.x;
    const int lane = tid & 31;
    const int w    = tid >> 5;
    const int gid  = lane >> 2;
    const int tig  = lane & 3;

    const int qb = (gridDim.x - 1) - blockIdx.x;   // heaviest blocks first
    const int bh = blockIdx.y;

    const float* Qg = g_q + ((size_t)bh * Nseq + qb * 64) * Dh;
    const float* Kg = g_k + (size_t)bh * Nseq * Dh;
    const float* Vg = g_v + (size_t)bh * Nseq * Dh;

    const float scale = 0.125f;

    // Load & pre-scale Q tile (64x64) into A-chunk layout
#pragma unroll
    for (int i = 0; i < 8; i++) {
        const int idx = tid + i * 128;
        const int r = idx >> 4, c4 = (idx & 15) * 4;
        float4 q = *(const float4*)(Qg + r * Dh + c4);
        const int m = r >> 4, gidl = r & 7, half = (r >> 3) & 1;
        const int kg = c4 >> 3, kh = (c4 >> 2) & 1;
        float* qp = Qs + (m * 8 + kg) * 132 + half + 2 * kh;
        const float v[4] = {q.x * scale, q.y * scale, q.z * scale, q.w * scale};
#pragma unroll
        for (int u = 0; u < 4; u++) qp[(gidl * 4 + u) * 4] = f2tf32(v[u]);
    }

    // per-thread row state (replicated across the 4-lane quad)
    float m_top = -INFINITY, m_bot = -INFINITY;
    float l_top = 0.f, l_bot = 0.f;

    float oacc[8][4];
#pragma unroll
    for (int nj = 0; nj < 8; nj++)
#pragma unroll
        for (int q = 0; q < 4; q++) oacc[nj][q] = 0.f;

    float4 kS[4], vS[4];  // staging
    auto ldg_kv = [&](int j) {
        const float* Kt = Kg + (size_t)j * 32 * Dh;
        const float* Vt = Vg + (size_t)j * 32 * Dh;
#pragma unroll
        for (int i = 0; i < 4; i++) {
            const int idx = tid + i * 128;
            const int r = idx >> 4, c4 = (idx & 15) * 4;
            kS[i] = *(const float4*)(Kt + r * Dh + c4);
            vS[i] = *(const float4*)(Vt + r * Dh + c4);
        }
    };

    const int ntiles = 2 * qb + 2;
    ldg_kv(0);
    for (int j = 0; j < ntiles; j++) {
        // store K/V tiles into B-chunk layouts
#pragma unroll
        for (int i = 0; i < 4; i++) {
            const int idx = tid + i * 128;
            const int r = idx >> 4, c4 = (idx & 15) * 4;
            {   // K: value (seqrow r, col d) -> chunk(nb=r/8, kg=d/8)
                const int nb = r >> 3, gidb = r & 7;
                const int kg = c4 >> 3, kh = (c4 >> 2) & 1;
                float* kp = Ks + (nb * 8 + kg) * 66 + kh;
                const float v[4] = {kS[i].x, kS[i].y, kS[i].z, kS[i].w};
#pragma unroll
                for (int u = 0; u < 4; u++) kp[(gidb * 4 + u) * 2] = f2tf32(v[u]);
            }
            {   // V: value (seqrow r = k-dim, col d = n-dim) -> chunk(nb=d/8, kg=r/8)
                const int nb = c4 >> 3;
                const int kg = r >> 3, kh = (r >> 2) & 1, tv = r & 3;
                float* vp = Vs + (nb * 4 + kg) * 66 + kh;
                const float v[4] = {vS[i].x, vS[i].y, vS[i].z, vS[i].w};
#pragma unroll
                for (int u = 0; u < 4; u++)
                    vp[(((c4 & 7) + u) * 4 + tv) * 2] = f2tf32(v[u]);
            }
        }
        __syncthreads();
        if (j + 1 < ntiles) ldg_kv(j + 1);

        // ---- S = Qs * Ks^T : warp rows w*16..+15, cols 0..31 ----
        float sacc[4][4];
#pragma unroll
        for (int nb = 0; nb < 4; nb++)
#pragma unroll
            for (int q = 0; q < 4; q++) sacc[nb][q] = 0.f;

#pragma unroll
        for (int kg = 0; kg < 8; kg++) {
            const float4 av = *(const float4*)(Qs + (w * 8 + kg) * 132 + lane * 4);
            unsigned af[4];
            af[0] = __float_as_uint(av.x); af[1] = __float_as_uint(av.y);
            af[2] = __float_as_uint(av.z); af[3] = __float_as_uint(av.w);
#pragma unroll
            for (int nb = 0; nb < 4; nb++) {
                const float2 bv = *(const float2*)(Ks + (nb * 8 + kg) * 66 + lane * 2);
                unsigned bf[2];
                bf[0] = __float_as_uint(bv.x); bf[1] = __float_as_uint(bv.y);
                mma_tf32(sacc[nb], af, bf);
            }
        }

        // causal mask (in fragments)
        if (j >= 2 * qb) {
            const int r0g = qb * 64 + w * 16 + gid;
            const int r1g = r0g + 8;
#pragma unroll
            for (int nb = 0; nb < 4; nb++) {
                const int cg = j * 32 + nb * 8 + 2 * tig;
                if (cg     > r0g) sacc[nb][0] = -INFINITY;
                if (cg + 1 > r0g) sacc[nb][1] = -INFINITY;
                if (cg     > r1g) sacc[nb][2] = -INFINITY;
                if (cg + 1 > r1g) sacc[nb][3] = -INFINITY;
            }
        }

        // ---- online softmax, register-resident (quad shuffles) ----
        float mt_t = m_top, mt_b = m_bot;
#pragma unroll
        for (int nb = 0; nb < 4; nb++) {
            mt_t = fmaxf(mt_t, fmaxf(sacc[nb][0], sacc[nb][1]));
            mt_b = fmaxf(mt_b, fmaxf(sacc[nb][2], sacc[nb][3]));
        }
        mt_t = fmaxf(mt_t, __shfl_xor_sync(0xffffffffu, mt_t, 1));
        mt_t = fmaxf(mt_t, __shfl_xor_sync(0xffffffffu, mt_t, 2));
        mt_b = fmaxf(mt_b, __shfl_xor_sync(0xffffffffu, mt_b, 1));
        mt_b = fmaxf(mt_b, __shfl_xor_sync(0xffffffffu, mt_b, 2));

        const float sc_t = __expf(m_top - mt_t);
        const float sc_b = __expf(m_bot - mt_b);
        float ps_t = 0.f, ps_b = 0.f;

        float* sbase = Ss + w * 4 * 132;
#pragma unroll
        for (int nb = 0; nb < 4; nb++) {
            float p[4];
            p[0] = __expf(sacc[nb][0] - mt_t);
            p[1] = __expf(sacc[nb][1] - mt_t);
            p[2] = __expf(sacc[nb][2] - mt_b);
            p[3] = __expf(sacc[nb][3] - mt_b);
            ps_t += p[0] + p[1];
            ps_b += p[2] + p[3];
            // store into A-chunk layout for the PV mma
#pragma unroll
            for (int q = 0; q < 4; q++) {
                const int par  = q & 1;
                const int half = q >> 1;
                const int kin  = 2 * tig + par;
                const int tigA = kin & 3;
                const int khA  = kin >> 2;
                sbase[nb * 132 + (gid * 4 + tigA) * 4 + half + 2 * khA] = f2tf32(p[q]);
            }
        }
        ps_t += __shfl_xor_sync(0xffffffffu, ps_t, 1);
        ps_t += __shfl_xor_sync(0xffffffffu, ps_t, 2);
        ps_b += __shfl_xor_sync(0xffffffffu, ps_b, 1);
        ps_b += __shfl_xor_sync(0xffffffffu, ps_b, 2);

        l_top = l_top * sc_t + ps_t;  m_top = mt_t;
        l_bot = l_bot * sc_b + ps_b;  m_bot = mt_b;

        __syncwarp();   // Ss is warp-private: warp-level ordering suffices

        // ---- O = O*rescale + P*V ----
#pragma unroll
        for (int nj = 0; nj < 8; nj++) {
            oacc[nj][0] *= sc_t; oacc[nj][1] *= sc_t;
            oacc[nj][2] *= sc_b; oacc[nj][3] *= sc_b;
        }
#pragma unroll
        for (int kg = 0; kg < 4; kg++) {
            const float4 av = *(const float4*)(sbase + kg * 132 + lane * 4);
            unsigned af[4];
            af[0] = __float_as_uint(av.x); af[1] = __float_as_uint(av.y);
            af[2] = __float_as_uint(av.z); af[3] = __float_as_uint(av.w);
#pragma unroll
            for (int nb = 0; nb < 8; nb++) {
                const float2 bv = *(const float2*)(Vs + (nb * 4 + kg) * 66 + lane * 2);
                unsigned bf[2];
                bf[0] = __float_as_uint(bv.x); bf[1] = __float_as_uint(bv.y);
                mma_tf32(oacc[nb], af, bf);
            }
        }
        __syncthreads();   // protect Ks/Vs before next iteration's stores
    }

    const int b = bh >> 4, h = bh & 15;
    const float inv_top = 1.f / l_top;
    const float inv_bot = 1.f / l_bot;
    const int n_top = qb * 64 + w * 16 + gid;
    const int n_bot = n_top + 8;
#pragma unroll
    for (int nj = 0; nj < 8; nj++) {
        const int c = nj * 8 + 2 * tig;
        float2 v0, v1;
        v0.x = oacc[nj][0] * inv_top; v0.y = oacc[nj][1] * inv_top;
        v1.x = oacc[nj][2] * inv_bot; v1.y = oacc[nj][3] * inv_bot;
        *(float2*)(g_ao + ((size_t)(b * Nseq + n_top)) * (Hh * Dh) + h * Dh + c) = v0;
        *(float2*)(g_ao + ((size_t)(b * Nseq + n_bot)) * (Hh * Dh) + h * Dh + c) = v1;
    }
}

// ---------------------------------------------------------------------------
extern "C" void kernel_launch(void* const* d_in, const int* in_sizes, int n_in,
                              void* d_out, int out_size)
{
    const float* x    = (const float*)d_in[0];
    const float* Wqkv = (const float*)d_in[1];
    const float* bqkv = (const float*)d_in[2];
    const float* Wout = (const float*)d_in[3];
    const float* bout = (const float*)d_in[4];
    float* out = (float*)d_out;

    // K1: QKV projection + de-interleave scatter. C is [4096, 3072].
    gemm_tf32_kernel<0><<<dim3(3072 / 128, 4096 / 128), 256>>>(x, Wqkv, bqkv, nullptr);

    // K2: causal flash attention. grid (N/64, B*H).
    flash_kernel<<<dim3(Nseq / 64, Bsz * Hh), 128>>>();

    // K3: output projection. C is [4096, 1024].
    gemm_tf32_kernel<1><<<dim3(1024 / 128, 4096 / 128), 256>>>(nullptr, Wout, bout, out);
}

// round 5
// speedup vs baseline: 5.4891x; 1.1872x over previous
#include <cuda_runtime.h>
#include <math.h>

#define Bsz  2
#define Nseq 2048
#define Emb  1024
#define Hh   16
#define Dh   64

// Scratch (allocation-free: __device__ globals)
__device__ float g_q [Bsz * Hh * Nseq * Dh];   // [B,H,N,D] (tf32-rounded)
__device__ float g_k [Bsz * Hh * Nseq * Dh];
__device__ float g_v [Bsz * Hh * Nseq * Dh];
__device__ float g_ao[Bsz * Nseq * Hh * Dh];   // [B,N,H*D] (tf32-rounded)
__device__ float g_x [Bsz * Nseq * Emb];       // tf32-rounded x
__device__ float g_wq[3 * Hh * Dh * Emb];      // tf32-rounded Wqkv
__device__ float g_wo[Emb * Hh * Dh];          // tf32-rounded Wout

// ---------------------------------------------------------------------------
// helpers
// ---------------------------------------------------------------------------
__device__ __forceinline__ float f2tf32(float f) {
    unsigned r;
    asm("cvt.rna.tf32.f32 %0, %1;" : "=r"(r) : "f"(f));
    return __uint_as_float(r);
}

__device__ __forceinline__ void mma_tf32(float* c, const unsigned* a, const unsigned* b) {
    asm volatile(
        "mma.sync.aligned.m16n8k8.row.col.f32.tf32.tf32.f32 "
        "{%0,%1,%2,%3},{%4,%5,%6,%7},{%8,%9},{%0,%1,%2,%3};"
        : "+f"(c[0]), "+f"(c[1]), "+f"(c[2]), "+f"(c[3])
        : "r"(a[0]), "r"(a[1]), "r"(a[2]), "r"(a[3]), "r"(b[0]), "r"(b[1]));
}

__device__ __forceinline__ void ldsm_x4(unsigned& r0, unsigned& r1, unsigned& r2, unsigned& r3,
                                        unsigned saddr) {
    asm volatile("ldmatrix.sync.aligned.m8n8.x4.shared.b16 {%0,%1,%2,%3}, [%4];"
                 : "=r"(r0), "=r"(r1), "=r"(r2), "=r"(r3) : "r"(saddr));
}

__device__ __forceinline__ void cp16(void* dst_smem, const void* src_gmem) {
    unsigned d = (unsigned)__cvta_generic_to_shared(dst_smem);
    asm volatile("cp.async.cg.shared.global [%0], [%1], 16;" :: "r"(d), "l"(src_gmem));
}

// ---------------------------------------------------------------------------
// tf32 pre-convert pass
// ---------------------------------------------------------------------------
__global__ void cvt_tf32_kernel(const float4* __restrict__ in, float4* __restrict__ out, int n4)
{
    const int i = blockIdx.x * 256 + threadIdx.x;
    if (i < n4) {
        float4 v = in[i];
        float4 r;
        r.x = f2tf32(v.x); r.y = f2tf32(v.y); r.z = f2tf32(v.z); r.w = f2tf32(v.w);
        out[i] = r;
    }
}

// ---------------------------------------------------------------------------
// TF32 GEMM: C[r][c] = sum_k A[r][k] * W[c][k] + bias[c]
// 128x128 block tile, BK=32, 256 threads = 8 warps (4 x 2), warp tile 32x64.
// cp.async 2-stage pipeline, 128B-swizzled smem, ldmatrix fragment loads.
// Inputs are pre-rounded to tf32. MODE 0: scatter to g_q/g_k/g_v (tf32-rounded);
// MODE 1: plain write to out.
// Dynamic smem: 2*(128*32)*2 floats = 64 KB.
// ---------------------------------------------------------------------------
template <int MODE>
__global__ void __launch_bounds__(256, 2) gemm_tf32_kernel(const float* __restrict__ bias,
                                                           float* __restrict__ out)
{
    extern __shared__ float smem[];
    float* Asm = smem;          // 2 stages x 4096 floats
    float* Wsm = smem + 8192;   // 2 stages x 4096 floats

    const float* Ain = (MODE == 0) ? g_x  : g_ao;
    const float* Win = (MODE == 0) ? g_wq : g_wo;

    const int tid  = threadIdx.x;
    const int lane = tid & 31;
    const int warp = tid >> 5;
    const int wm   = warp & 3;         // 0..3 : 32-row group
    const int wn   = warp >> 2;        // 0..1 : 64-col group
    const int bm = blockIdx.y * 128;
    const int bn = blockIdx.x * 128;

    const int gid = lane >> 2;
    const int tig = lane & 3;

    // ldmatrix per-lane address components
    const int a_row  = lane & 15;
    const int a_cbit = lane >> 4;
    const int b_row  = (lane & 7) + ((lane & 16) >> 1);
    const int b_cbit = (lane >> 3) & 1;

    float acc[2][8][4];
#pragma unroll
    for (int mi = 0; mi < 2; mi++)
#pragma unroll
        for (int nj = 0; nj < 8; nj++)
#pragma unroll
            for (int q = 0; q < 4; q++) acc[mi][nj][q] = 0.f;

    auto cp_tile = [&](int kt, int stage) {
        const float* Ab = Ain + (size_t)bm * Emb + kt * 32;
        const float* Wb = Win + (size_t)bn * Emb + kt * 32;
        float* as = Asm + stage * 4096;
        float* ws = Wsm + stage * 4096;
#pragma unroll
        for (int i = 0; i < 4; i++) {
            const int idx = tid + i * 256;          // 0..1023
            const int row = idx >> 3;               // 0..127
            const int ch  = idx & 7;                // 16B chunk
            const int off = row * 32 + ((ch ^ (row & 7)) << 2);
            cp16(as + off, Ab + (size_t)row * Emb + ch * 4);
            cp16(ws + off, Wb + (size_t)row * Emb + ch * 4);
        }
        asm volatile("cp.async.commit_group;");
    };

    const int NT = Emb / 32;
    cp_tile(0, 0);

    for (int kt = 0; kt < NT; kt++) {
        if (kt + 1 < NT) {
            cp_tile(kt + 1, (kt + 1) & 1);
            asm volatile("cp.async.wait_group 1;");
        } else {
            asm volatile("cp.async.wait_group 0;");
        }
        __syncthreads();

        const float* as = Asm + (kt & 1) * 4096;
        const float* ws = Wsm + (kt & 1) * 4096;

#pragma unroll
        for (int kk8 = 0; kk8 < 4; kk8++) {
            unsigned afrag[2][4];
#pragma unroll
            for (int mi = 0; mi < 2; mi++) {
                const int row = wm * 32 + mi * 16 + a_row;
                const int ch  = kk8 * 2 + a_cbit;
                const unsigned sa = (unsigned)__cvta_generic_to_shared(
                    as + row * 32 + ((ch ^ (row & 7)) << 2));
                ldsm_x4(afrag[mi][0], afrag[mi][1], afrag[mi][2], afrag[mi][3], sa);
            }
            unsigned bfrag[8][2];
#pragma unroll
            for (int nj2 = 0; nj2 < 4; nj2++) {
                const int row = wn * 64 + nj2 * 16 + b_row;
                const int ch  = kk8 * 2 + b_cbit;
                const unsigned sb = (unsigned)__cvta_generic_to_shared(
                    ws + row * 32 + ((ch ^ (row & 7)) << 2));
                ldsm_x4(bfrag[nj2 * 2][0], bfrag[nj2 * 2][1],
                        bfrag[nj2 * 2 + 1][0], bfrag[nj2 * 2 + 1][1], sb);
            }
#pragma unroll
            for (int mi = 0; mi < 2; mi++)
#pragma unroll
                for (int nj = 0; nj < 8; nj++)
                    mma_tf32(acc[mi][nj], afrag[mi], bfrag[nj]);
        }
        __syncthreads();
    }

    // epilogue
#pragma unroll
    for (int mi = 0; mi < 2; mi++) {
        const int r_top = bm + wm * 32 + mi * 16 + gid;
        const int r_bot = r_top + 8;
#pragma unroll
        for (int nj = 0; nj < 8; nj++) {
            const int c = bn + wn * 64 + nj * 8 + 2 * tig;
            if (MODE == 0) {
#pragma unroll
                for (int q = 0; q < 4; q++) {
                    const int row = (q < 2) ? r_top : r_bot;
                    const int col = c + (q & 1);
                    const int b = row >> 11;
                    const int n = row & 2047;
                    const int s = col % 3;
                    const int h = col / 192;
                    const int d = (col % 192) / 3;
                    const float val = f2tf32(acc[mi][nj][q] + bias[col]);
                    float* dst = (s == 0) ? g_q : (s == 1) ? g_k : g_v;
                    dst[(((size_t)(b * Hh + h)) * Nseq + n) * Dh + d] = val;
                }
            } else {
                const float2 bv = *(const float2*)(bias + c);
                float2 v0, v1;
                v0.x = acc[mi][nj][0] + bv.x; v0.y = acc[mi][nj][1] + bv.y;
                v1.x = acc[mi][nj][2] + bv.x; v1.y = acc[mi][nj][3] + bv.y;
                *(float2*)(out + (size_t)r_top * Emb + c) = v0;
                *(float2*)(out + (size_t)r_bot * Emb + c) = v1;
            }
        }
    }
}

// ---------------------------------------------------------------------------
// Flash attention, TF32 mma, register-resident online softmax.
// grid = (N/64, B*H), 128 threads = 4 warps. BR=64, BC=32, D=64.
// q/k/v are pre-rounded to tf32 by K1 — no cvts in the hot loop.
// ---------------------------------------------------------------------------
__global__ void __launch_bounds__(128) flash_kernel()
{
    // Fragment-ordered smem
    __shared__ __align__(16) float Qs[32 * 132];  // A-chunks (m 0..3, kg 0..7)
    __shared__ __align__(16) float Ks[32 * 66];   // B-chunks (nb 0..3, kg 0..7)
    __shared__ __align__(16) float Vs[32 * 66];   // B-chunks (nb 0..7 [d], kg 0..3 [c])
    __shared__ __align__(16) float Ss[16 * 132];  // A-chunks per warp (w, kg 0..3)

    const int tid  = threadIdx.x;
    const int lane = tid & 31;
    const int w    = tid >> 5;
    const int gid  = lane >> 2;
    const int tig  = lane & 3;

    const int qb = (gridDim.x - 1) - blockIdx.x;   // heaviest blocks first
    const int bh = blockIdx.y;

    const float* Qg = g_q + ((size_t)bh * Nseq + qb * 64) * Dh;
    const float* Kg = g_k + (size_t)bh * Nseq * Dh;
    const float* Vg = g_v + (size_t)bh * Nseq * Dh;

    const float scale = 0.125f;   // exact on tf32 values (exponent-only)

    // Load & pre-scale Q tile (64x64) into A-chunk layout
#pragma unroll
    for (int i = 0; i < 8; i++) {
        const int idx = tid + i * 128;
        const int r = idx >> 4, c4 = (idx & 15) * 4;
        float4 q = *(const float4*)(Qg + r * Dh + c4);
        const int m = r >> 4, gidl = r & 7, half = (r >> 3) & 1;
        const int kg = c4 >> 3, kh = (c4 >> 2) & 1;
        float* qp = Qs + (m * 8 + kg) * 132 + half + 2 * kh;
        const float v[4] = {q.x * scale, q.y * scale, q.z * scale, q.w * scale};
#pragma unroll
        for (int u = 0; u < 4; u++) qp[(gidl * 4 + u) * 4] = v[u];
    }

    float m_top = -INFINITY, m_bot = -INFINITY;
    float l_top = 0.f, l_bot = 0.f;

    float oacc[8][4];
#pragma unroll
    for (int nj = 0; nj < 8; nj++)
#pragma unroll
        for (int q = 0; q < 4; q++) oacc[nj][q] = 0.f;

    float4 kS[4], vS[4];  // staging
    auto ldg_kv = [&](int j) {
        const float* Kt = Kg + (size_t)j * 32 * Dh;
        const float* Vt = Vg + (size_t)j * 32 * Dh;
#pragma unroll
        for (int i = 0; i < 4; i++) {
            const int idx = tid + i * 128;
            const int r = idx >> 4, c4 = (idx & 15) * 4;
            kS[i] = *(const float4*)(Kt + r * Dh + c4);
            vS[i] = *(const float4*)(Vt + r * Dh + c4);
        }
    };

    const int ntiles = 2 * qb + 2;
    ldg_kv(0);
    for (int j = 0; j < ntiles; j++) {
        // store K/V tiles into B-chunk layouts (already tf32)
#pragma unroll
        for (int i = 0; i < 4; i++) {
            const int idx = tid + i * 128;
            const int r = idx >> 4, c4 = (idx & 15) * 4;
            {   // K: (seqrow r, col d) -> chunk(nb=r/8, kg=d/8)
                const int nb = r >> 3, gidb = r & 7;
                const int kg = c4 >> 3, kh = (c4 >> 2) & 1;
                float* kp = Ks + (nb * 8 + kg) * 66 + kh;
                const float v[4] = {kS[i].x, kS[i].y, kS[i].z, kS[i].w};
#pragma unroll
                for (int u = 0; u < 4; u++) kp[(gidb * 4 + u) * 2] = v[u];
            }
            {   // V: (seqrow r = k-dim, col d = n-dim) -> chunk(nb=d/8, kg=r/8)
                const int nb = c4 >> 3;
                const int kg = r >> 3, kh = (r >> 2) & 1, tv = r & 3;
                float* vp = Vs + (nb * 4 + kg) * 66 + kh;
                const float v[4] = {vS[i].x, vS[i].y, vS[i].z, vS[i].w};
#pragma unroll
                for (int u = 0; u < 4; u++)
                    vp[(((c4 & 7) + u) * 4 + tv) * 2] = v[u];
            }
        }
        __syncthreads();
        if (j + 1 < ntiles) ldg_kv(j + 1);

        // ---- S = Qs * Ks^T ----
        float sacc[4][4];
#pragma unroll
        for (int nb = 0; nb < 4; nb++)
#pragma unroll
            for (int q = 0; q < 4; q++) sacc[nb][q] = 0.f;

#pragma unroll
        for (int kg = 0; kg < 8; kg++) {
            const float4 av = *(const float4*)(Qs + (w * 8 + kg) * 132 + lane * 4);
            unsigned af[4];
            af[0] = __float_as_uint(av.x); af[1] = __float_as_uint(av.y);
            af[2] = __float_as_uint(av.z); af[3] = __float_as_uint(av.w);
#pragma unroll
            for (int nb = 0; nb < 4; nb++) {
                const float2 bv = *(const float2*)(Ks + (nb * 8 + kg) * 66 + lane * 2);
                unsigned bf[2];
                bf[0] = __float_as_uint(bv.x); bf[1] = __float_as_uint(bv.y);
                mma_tf32(sacc[nb], af, bf);
            }
        }

        // causal mask
        if (j >= 2 * qb) {
            const int r0g = qb * 64 + w * 16 + gid;
            const int r1g = r0g + 8;
#pragma unroll
            for (int nb = 0; nb < 4; nb++) {
                const int cg = j * 32 + nb * 8 + 2 * tig;
                if (cg     > r0g) sacc[nb][0] = -INFINITY;
                if (cg + 1 > r0g) sacc[nb][1] = -INFINITY;
                if (cg     > r1g) sacc[nb][2] = -INFINITY;
                if (cg + 1 > r1g) sacc[nb][3] = -INFINITY;
            }
        }

        // ---- online softmax (quad shuffles) ----
        float mt_t = m_top, mt_b = m_bot;
#pragma unroll
        for (int nb = 0; nb < 4; nb++) {
            mt_t = fmaxf(mt_t, fmaxf(sacc[nb][0], sacc[nb][1]));
            mt_b = fmaxf(mt_b, fmaxf(sacc[nb][2], sacc[nb][3]));
        }
        mt_t = fmaxf(mt_t, __shfl_xor_sync(0xffffffffu, mt_t, 1));
        mt_t = fmaxf(mt_t, __shfl_xor_sync(0xffffffffu, mt_t, 2));
        mt_b = fmaxf(mt_b, __shfl_xor_sync(0xffffffffu, mt_b, 1));
        mt_b = fmaxf(mt_b, __shfl_xor_sync(0xffffffffu, mt_b, 2));

        const float sc_t = __expf(m_top - mt_t);
        const float sc_b = __expf(m_bot - mt_b);
        float ps_t = 0.f, ps_b = 0.f;

        float* sbase = Ss + w * 4 * 132;
#pragma unroll
        for (int nb = 0; nb < 4; nb++) {
            float p[4];
            p[0] = __expf(sacc[nb][0] - mt_t);
            p[1] = __expf(sacc[nb][1] - mt_t);
            p[2] = __expf(sacc[nb][2] - mt_b);
            p[3] = __expf(sacc[nb][3] - mt_b);
            ps_t += p[0] + p[1];
            ps_b += p[2] + p[3];
#pragma unroll
            for (int q = 0; q < 4; q++) {
                const int par  = q & 1;
                const int half = q >> 1;
                const int kin  = 2 * tig + par;
                const int tigA = kin & 3;
                const int khA  = kin >> 2;
                sbase[nb * 132 + (gid * 4 + tigA) * 4 + half + 2 * khA] = f2tf32(p[q]);
            }
        }
        ps_t += __shfl_xor_sync(0xffffffffu, ps_t, 1);
        ps_t += __shfl_xor_sync(0xffffffffu, ps_t, 2);
        ps_b += __shfl_xor_sync(0xffffffffu, ps_b, 1);
        ps_b += __shfl_xor_sync(0xffffffffu, ps_b, 2);

        l_top = l_top * sc_t + ps_t;  m_top = mt_t;
        l_bot = l_bot * sc_b + ps_b;  m_bot = mt_b;

        __syncwarp();

        // ---- O = O*rescale + P*V ----
#pragma unroll
        for (int nj = 0; nj < 8; nj++) {
            oacc[nj][0] *= sc_t; oacc[nj][1] *= sc_t;
            oacc[nj][2] *= sc_b; oacc[nj][3] *= sc_b;
        }
#pragma unroll
        for (int kg = 0; kg < 4; kg++) {
            const float4 av = *(const float4*)(sbase + kg * 132 + lane * 4);
            unsigned af[4];
            af[0] = __float_as_uint(av.x); af[1] = __float_as_uint(av.y);
            af[2] = __float_as_uint(av.z); af[3] = __float_as_uint(av.w);
#pragma unroll
            for (int nb = 0; nb < 8; nb++) {
                const float2 bv = *(const float2*)(Vs + (nb * 4 + kg) * 66 + lane * 2);
                unsigned bf[2];
                bf[0] = __float_as_uint(bv.x); bf[1] = __float_as_uint(bv.y);
                mma_tf32(oacc[nb], af, bf);
            }
        }
        __syncthreads();
    }

    const int b = bh >> 4, h = bh & 15;
    const float inv_top = 1.f / l_top;
    const float inv_bot = 1.f / l_bot;
    const int n_top = qb * 64 + w * 16 + gid;
    const int n_bot = n_top + 8;
#pragma unroll
    for (int nj = 0; nj < 8; nj++) {
        const int c = nj * 8 + 2 * tig;
        float2 v0, v1;
        v0.x = f2tf32(oacc[nj][0] * inv_top); v0.y = f2tf32(oacc[nj][1] * inv_top);
        v1.x = f2tf32(oacc[nj][2] * inv_bot); v1.y = f2tf32(oacc[nj][3] * inv_bot);
        *(float2*)(g_ao + ((size_t)(b * Nseq + n_top)) * (Hh * Dh) + h * Dh + c) = v0;
        *(float2*)(g_ao + ((size_t)(b * Nseq + n_bot)) * (Hh * Dh) + h * Dh + c) = v1;
    }
}

// ---------------------------------------------------------------------------
extern "C" void kernel_launch(void* const* d_in, const int* in_sizes, int n_in,
                              void* d_out, int out_size)
{
    const float* x    = (const float*)d_in[0];
    const float* Wqkv = (const float*)d_in[1];
    const float* bqkv = (const float*)d_in[2];
    const float* Wout = (const float*)d_in[3];
    const float* bout = (const float*)d_in[4];
    float* out = (float*)d_out;

    // raise dynamic smem limit (idempotent; 64 KB)
    cudaFuncSetAttribute(gemm_tf32_kernel<0>, cudaFuncAttributeMaxDynamicSharedMemorySize, 65536);
    cudaFuncSetAttribute(gemm_tf32_kernel<1>, cudaFuncAttributeMaxDynamicSharedMemorySize, 65536);

    float *gx, *gwq, *gwo;
    cudaGetSymbolAddress((void**)&gx,  g_x);
    cudaGetSymbolAddress((void**)&gwq, g_wq);
    cudaGetSymbolAddress((void**)&gwo, g_wo);

    // K0: tf32 pre-conversion of x, Wqkv, Wout
    cvt_tf32_kernel<<<(Bsz * Nseq * Emb / 4 + 255) / 256, 256>>>((const float4*)x,    (float4*)gx,  Bsz * Nseq * Emb / 4);
    cvt_tf32_kernel<<<(3 * Hh * Dh * Emb / 4 + 255) / 256, 256>>>((const float4*)Wqkv, (float4*)gwq, 3 * Hh * Dh * Emb / 4);
    cvt_tf32_kernel<<<(Emb * Hh * Dh / 4 + 255) / 256, 256>>>((const float4*)Wout,  (float4*)gwo, Emb * Hh * Dh / 4);

    // K1: QKV projection + de-interleave scatter. C is [4096, 3072].
    gemm_tf32_kernel<0><<<dim3(3072 / 128, 4096 / 128), 256, 65536>>>(bqkv, nullptr);

    // K2: causal flash attention. grid (N/64, B*H).
    flash_kernel<<<dim3(Nseq / 64, Bsz * Hh), 128>>>();

    // K3: output projection. C is [4096, 1024].
    gemm_tf32_kernel<1><<<dim3(1024 / 128, 4096 / 128), 256, 65536>>>(bout, out);
}